// round 9
// baseline (speedup 1.0000x reference)
#include <cuda_runtime.h>
#include <math.h>

// A[b,i,j] = softmax_i(s_i + s_j + bias) = exp(s_i)/sum_i' exp(s_i')
// (s_j and bias cancel under softmax over axis=1). Output row (b,i,:) is a
// constant p[b,i] broadcast N wide.
//
// Two launches:
//  K1: e=exp(h.w) (4 rows/warp, MLP=8) + per-block partial sums (no atomics)
//  K2: fill — 8 rows/block, 256 threads, row-sequential register-lean body.
//      R8 lesson: store BW tracks resident warps; 512-thr/54-reg blocks
//      (occ 45%) only hit 5.0 TB/s. Keep the head amortized AND occ high.

#define MAX_BN   16384    // B*N for B=4, N=4096
#define K1_THREADS 256    // 8 warps * 4 rows = 32 rows/block
#define ROWS_PER_WARP 4
#define MAX_PART  1024
#define FILL_ROWS 8       // rows per fill block
#define FILL_THREADS 256

__device__ float g_e[MAX_BN];        // exp(s)
__device__ float g_part[MAX_PART];   // per-block partial sums

// ---- K1: dot + exp + block partial sum ----
__global__ void __launch_bounds__(K1_THREADS)
dot_exp_kernel(const float* __restrict__ h,
               const float* __restrict__ w,
               int BN, int D4) {
    __shared__ float s_warp[K1_THREADS / 32];

    const int warp = threadIdx.x >> 5;
    const int lane = threadIdx.x & 31;
    const int row0 = blockIdx.x * (K1_THREADS / 32 * ROWS_PER_WARP) + warp * ROWS_PER_WARP;

    const float4* wv = reinterpret_cast<const float4*>(w);
    float e_sum = 0.0f;

    if (D4 == 64 && row0 + ROWS_PER_WARP <= BN) {
        float4 b0 = __ldg(wv + lane);
        float4 b1 = __ldg(wv + lane + 32);
        // batch all 8 h loads up front (MLP=8)
        float4 a0[ROWS_PER_WARP], a1[ROWS_PER_WARP];
        #pragma unroll
        for (int r = 0; r < ROWS_PER_WARP; r++) {
            const float4* hr = reinterpret_cast<const float4*>(h) + (size_t)(row0 + r) * 64;
            a0[r] = __ldg(hr + lane);
            a1[r] = __ldg(hr + lane + 32);
        }
        #pragma unroll
        for (int r = 0; r < ROWS_PER_WARP; r++) {
            float acc = a0[r].x * b0.x + a0[r].y * b0.y + a0[r].z * b0.z + a0[r].w * b0.w
                      + a1[r].x * b1.x + a1[r].y * b1.y + a1[r].z * b1.z + a1[r].w * b1.w;
            #pragma unroll
            for (int o = 16; o; o >>= 1)
                acc += __shfl_xor_sync(0xFFFFFFFFu, acc, o);
            float ev = __expf(acc);
            if (lane == 0) {
                g_e[row0 + r] = ev;
                e_sum += ev;                 // sequential in r: deterministic
            }
        }
    } else {
        for (int r = 0; r < ROWS_PER_WARP; r++) {
            int row = row0 + r;
            if (row >= BN) break;
            const float4* hr = reinterpret_cast<const float4*>(h) + (size_t)row * D4;
            float acc = 0.0f;
            for (int c = lane; c < D4; c += 32) {
                float4 a = __ldg(hr + c);
                float4 b = __ldg(wv + c);
                acc += a.x * b.x + a.y * b.y + a.z * b.z + a.w * b.w;
            }
            #pragma unroll
            for (int o = 16; o; o >>= 1)
                acc += __shfl_xor_sync(0xFFFFFFFFu, acc, o);
            if (lane == 0) {
                float ev = __expf(acc);
                g_e[row] = ev;
                e_sum += ev;
            }
        }
    }

    if (lane == 0) s_warp[warp] = e_sum;
    __syncthreads();
    if (threadIdx.x == 0) {
        float p = 0.0f;
        #pragma unroll
        for (int i = 0; i < K1_THREADS / 32; i++) p += s_warp[i];  // fixed order
        g_part[blockIdx.x] = p;
    }
}

// ---- K2: amortized inv reduce + row-sequential lean fill ----
__global__ void __launch_bounds__(FILL_THREADS)
fill_kernel(const float* __restrict__ e,
            float4* __restrict__ out,
            int N4, int parts_per_batch) {
    __shared__ float inv_s;
    __shared__ float v_s[FILL_ROWS];

    const int tid = threadIdx.x;

    // warp 0: reduce this batch's partials in FIXED order (identical on every
    // block of the batch -> deterministic & consistent)
    if (tid < 32) {
        int base = blockIdx.y * parts_per_batch;
        int per_lane = parts_per_batch >> 5;          // 128/32 = 4
        float p = 0.0f;
        for (int k = 0; k < per_lane; k++)
            p += g_part[base + tid * per_lane + k];   // sequential per lane
        #pragma unroll
        for (int o = 16; o; o >>= 1)
            p += __shfl_xor_sync(0xFFFFFFFFu, p, o);
        if (tid == 0) inv_s = 1.0f / p;
    }
    __syncthreads();

    size_t row0 = (size_t)blockIdx.y * ((size_t)gridDim.x * FILL_ROWS)
                + (size_t)blockIdx.x * FILL_ROWS;
    if (tid < FILL_ROWS)
        v_s[tid] = e[row0 + tid] * inv_s;
    __syncthreads();

    // row-sequential, register-lean streaming (R1-shape body per row)
    float4* o = out + row0 * (size_t)N4;
    #pragma unroll
    for (int r = 0; r < FILL_ROWS; r++) {
        float v = v_s[r];
        float4 v4 = make_float4(v, v, v, v);
        #pragma unroll 4
        for (int c = tid; c < N4; c += FILL_THREADS)
            __stcs(o + c, v4);
        o += N4;
    }
}

extern "C" void kernel_launch(void* const* d_in, const int* in_sizes, int n_in,
                              void* d_out, int out_size) {
    const float* h = (const float*)d_in[0];
    const float* w = (const float*)d_in[1];
    // d_in[2] (bias) cancels in the softmax over axis=1 -> unused.

    int D  = in_sizes[1];                       // 256
    int BN = in_sizes[0] / D;                   // B*N = 16384
    int N  = (int)((long long)out_size / BN);   // 4096
    int B  = BN / N;                            // 4

    float* e = nullptr;
    cudaGetSymbolAddress((void**)&e, g_e);

    int rows_per_block = (K1_THREADS / 32) * ROWS_PER_WARP;     // 32
    int k1_blocks = (BN + rows_per_block - 1) / rows_per_block; // 512
    dot_exp_kernel<<<k1_blocks, K1_THREADS>>>(h, w, BN, D >> 2);

    int parts_per_batch = k1_blocks / B;                        // 128
    dim3 grid(N / FILL_ROWS, B);                                // 512 x 4
    fill_kernel<<<grid, FILL_THREADS>>>(e, (float4*)d_out, N >> 2, parts_per_batch);
}

// round 10
// speedup vs baseline: 1.0412x; 1.0412x over previous
#include <cuda_runtime.h>
#include <math.h>

// A[b,i,j] = softmax_i(s_i + s_j + bias) = exp(s_i)/sum_i' exp(s_i')
// (s_j and bias cancel under softmax over axis=1). Output row (b,i,:) is a
// constant p[b,i] broadcast N wide.
//
// K1: e=exp(h.w) (4 rows/warp, MLP=8) + per-block partial sums (no atomics)
// K2 (PDL secondary): vectorized inv head (1 LDG.128/lane, fixed order) +
//     4 rows/block lean streaming fill. cudaGridDependencySynchronize()
//     placed after setup so launch ramp overlaps K1.

#define MAX_BN   16384    // B*N for B=4, N=4096
#define K1_THREADS 256    // 8 warps * 4 rows = 32 rows/block
#define ROWS_PER_WARP 4
#define MAX_PART  1024
#define FILL_ROWS 4       // rows per fill block
#define FILL_THREADS 256

__device__ float g_e[MAX_BN];        // exp(s)
__device__ float g_part[MAX_PART];   // per-block partial sums

// ---- K1: dot + exp + block partial sum ----
__global__ void __launch_bounds__(K1_THREADS)
dot_exp_kernel(const float* __restrict__ h,
               const float* __restrict__ w,
               int BN, int D4) {
    __shared__ float s_warp[K1_THREADS / 32];

    const int warp = threadIdx.x >> 5;
    const int lane = threadIdx.x & 31;
    const int row0 = blockIdx.x * (K1_THREADS / 32 * ROWS_PER_WARP) + warp * ROWS_PER_WARP;

    const float4* wv = reinterpret_cast<const float4*>(w);
    float e_sum = 0.0f;

    if (D4 == 64 && row0 + ROWS_PER_WARP <= BN) {
        float4 b0 = __ldg(wv + lane);
        float4 b1 = __ldg(wv + lane + 32);
        // batch all 8 h loads up front (MLP=8)
        float4 a0[ROWS_PER_WARP], a1[ROWS_PER_WARP];
        #pragma unroll
        for (int r = 0; r < ROWS_PER_WARP; r++) {
            const float4* hr = reinterpret_cast<const float4*>(h) + (size_t)(row0 + r) * 64;
            a0[r] = __ldg(hr + lane);
            a1[r] = __ldg(hr + lane + 32);
        }
        #pragma unroll
        for (int r = 0; r < ROWS_PER_WARP; r++) {
            float acc = a0[r].x * b0.x + a0[r].y * b0.y + a0[r].z * b0.z + a0[r].w * b0.w
                      + a1[r].x * b1.x + a1[r].y * b1.y + a1[r].z * b1.z + a1[r].w * b1.w;
            #pragma unroll
            for (int o = 16; o; o >>= 1)
                acc += __shfl_xor_sync(0xFFFFFFFFu, acc, o);
            float ev = __expf(acc);
            if (lane == 0) {
                g_e[row0 + r] = ev;
                e_sum += ev;                 // sequential in r: deterministic
            }
        }
    } else {
        for (int r = 0; r < ROWS_PER_WARP; r++) {
            int row = row0 + r;
            if (row >= BN) break;
            const float4* hr = reinterpret_cast<const float4*>(h) + (size_t)row * D4;
            float acc = 0.0f;
            for (int c = lane; c < D4; c += 32) {
                float4 a = __ldg(hr + c);
                float4 b = __ldg(wv + c);
                acc += a.x * b.x + a.y * b.y + a.z * b.z + a.w * b.w;
            }
            #pragma unroll
            for (int o = 16; o; o >>= 1)
                acc += __shfl_xor_sync(0xFFFFFFFFu, acc, o);
            if (lane == 0) {
                float ev = __expf(acc);
                g_e[row] = ev;
                e_sum += ev;
            }
        }
    }

    if (lane == 0) s_warp[warp] = e_sum;
    __syncthreads();
    if (threadIdx.x == 0) {
        float p = 0.0f;
        #pragma unroll
        for (int i = 0; i < K1_THREADS / 32; i++) p += s_warp[i];  // fixed order
        g_part[blockIdx.x] = p;
    }
}

// ---- K2: PDL secondary. Vectorized inv head + lean 4-row fill ----
__global__ void __launch_bounds__(FILL_THREADS)
fill_kernel(const float* __restrict__ e,
            float4* __restrict__ out,
            int N4, int parts_per_batch) {
    __shared__ float inv_s;
    __shared__ float v_s[FILL_ROWS];

    const int tid = threadIdx.x;

    // setup BEFORE the dependency sync (overlaps with K1 under PDL)
    size_t row0 = (size_t)blockIdx.y * ((size_t)gridDim.x * FILL_ROWS)
                + (size_t)blockIdx.x * FILL_ROWS;
    float4* o = out + row0 * (size_t)N4;
    const float4* p4 = reinterpret_cast<const float4*>(g_part)
                     + ((size_t)blockIdx.y * parts_per_batch >> 2);
    int nvec = parts_per_batch >> 2;              // 32 for 128 partials

    cudaGridDependencySynchronize();              // wait for K1's results

    // warp 0: one LDG.128 per lane, fixed intra/inter-lane order -> deterministic
    if (tid < 32) {
        float p = 0.0f;
        for (int k = tid; k < nvec; k += 32) {
            float4 q = __ldg(p4 + k);
            p += (q.x + q.y) + (q.z + q.w);
        }
        #pragma unroll
        for (int oo = 16; oo; oo >>= 1)
            p += __shfl_xor_sync(0xFFFFFFFFu, p, oo);
        if (tid == 0) inv_s = 1.0f / p;
    }
    __syncthreads();

    if (tid < FILL_ROWS)
        v_s[tid] = e[row0 + tid] * inv_s;
    __syncthreads();

    // row-sequential register-lean streaming
    #pragma unroll
    for (int r = 0; r < FILL_ROWS; r++) {
        float v = v_s[r];
        float4 v4 = make_float4(v, v, v, v);
        #pragma unroll 4
        for (int c = tid; c < N4; c += FILL_THREADS)
            __stcs(o + c, v4);
        o += N4;
    }
}

extern "C" void kernel_launch(void* const* d_in, const int* in_sizes, int n_in,
                              void* d_out, int out_size) {
    const float* h = (const float*)d_in[0];
    const float* w = (const float*)d_in[1];
    // d_in[2] (bias) cancels in the softmax over axis=1 -> unused.

    int D  = in_sizes[1];                       // 256
    int BN = in_sizes[0] / D;                   // B*N = 16384
    int N  = (int)((long long)out_size / BN);   // 4096
    int B  = BN / N;                            // 4

    float* e = nullptr;
    cudaGetSymbolAddress((void**)&e, g_e);

    int rows_per_block = (K1_THREADS / 32) * ROWS_PER_WARP;     // 32
    int k1_blocks = (BN + rows_per_block - 1) / rows_per_block; // 512
    dot_exp_kernel<<<k1_blocks, K1_THREADS>>>(h, w, BN, D >> 2);

    int parts_per_batch = k1_blocks / B;                        // 128

    // PDL launch: fill may begin (setup) while K1 runs; data gated by
    // cudaGridDependencySynchronize() inside the kernel.
    cudaLaunchConfig_t cfg = {};
    cfg.gridDim  = dim3(N / FILL_ROWS, B);                      // 1024 x 4
    cfg.blockDim = dim3(FILL_THREADS);
    cfg.stream   = 0;
    cudaLaunchAttribute attrs[1];
    attrs[0].id = cudaLaunchAttributeProgrammaticStreamSerialization;
    attrs[0].val.programmaticStreamSerializationAllowed = 1;
    cfg.attrs    = attrs;
    cfg.numAttrs = 1;
    cudaLaunchKernelEx(&cfg, fill_kernel, (const float*)e, (float4*)d_out,
                       N >> 2, parts_per_batch);
}